// round 1
// baseline (speedup 1.0000x reference)
#include <cuda_runtime.h>
#include <math.h>

#define NMAX 100000
#define EMAX 1600000
#define FULL 0xffffffffu

// ---------------- scratch (static __device__, no allocs) ----------------
__device__ float g_A[NMAX * 128];    // projected features h = in @ W
__device__ float g_B[NMAX * 128];    // conv accumulate / node features
__device__ float g_D[NMAX * 128];    // residual projection x @ Wr
__device__ float g_hmu[NMAX * 64];
__device__ float g_hls[NMAX * 64];
__device__ float g_L1[EMAX];
__device__ float g_L2[EMAX];
__device__ float g_T2[EMAX];
__device__ float g_Tmu[EMAX];
__device__ float g_Tls[EMAX];
__device__ float g_as1[NMAX], g_ad1[NMAX], g_as2[NMAX], g_ad2[NMAX];
__device__ float g_m1[NMAX], g_m2[NMAX], g_sum1[NMAX], g_sum2[NMAX];
__device__ float g_sa1[NMAX], g_sa2[NMAX], g_sl1[NMAX], g_sl2[NMAX];
__device__ float g_ts2[NMAX], g_tsmu[NMAX], g_tsls[NMAX], g_cnt[NMAX];
__device__ float g_st2[NMAX], g_stmu[NMAX], g_stls[NMAX];
__device__ float g_wa[48];           // We@ae for conv2 / mu / ls (16 each)

// ---------------- device helpers ----------------
__device__ __forceinline__ float leaky(float v) { return v > 0.f ? v : 0.2f * v; }

__device__ __forceinline__ void atomicMaxF(float* addr, float v) {
    if (v >= 0.f) atomicMax((int*)addr, __float_as_int(v));
    else          atomicMin((unsigned int*)addr, (unsigned int)__float_as_int(v));
}

__device__ __forceinline__ void redAdd4(float* p, float4 v) {
    asm volatile("red.global.add.v4.f32 [%0], {%1,%2,%3,%4};"
                 :: "l"(p), "f"(v.x), "f"(v.y), "f"(v.z), "f"(v.w) : "memory");
}

// ---------------- GEMM: Y[n,C] = X[n,128] @ W[128,C] ----------------
template <int C>
__global__ void gemm_k(const float* __restrict__ X, const float* __restrict__ W,
                       float* __restrict__ Y, int n) {
    __shared__ float Wsh[64 * C];
    __shared__ float Xs[8 * 128];
    const int j = threadIdx.x;            // 0..C-1
    const int row0 = blockIdx.x * 8;
    float acc[8];
#pragma unroll
    for (int r = 0; r < 8; r++) acc[r] = 0.f;
    for (int idx = j; idx < 8 * 128; idx += C) {
        int r = idx >> 7, k = idx & 127;
        Xs[idx] = (row0 + r < n) ? X[(size_t)(row0 + r) * 128 + k] : 0.f;
    }
    for (int kb = 0; kb < 128; kb += 64) {
        __syncthreads();
        for (int idx = j; idx < 64 * C; idx += C)
            Wsh[idx] = W[(size_t)(kb + idx / C) * C + (idx % C)];
        __syncthreads();
#pragma unroll
        for (int k = 0; k < 64; k++) {
            float w = Wsh[k * C + j];
#pragma unroll
            for (int r = 0; r < 8; r++) acc[r] = fmaf(Xs[r * 128 + kb + k], w, acc[r]);
        }
    }
#pragma unroll
    for (int r = 0; r < 8; r++)
        if (row0 + r < n) Y[(size_t)(row0 + r) * C + j] = acc[r];
}

// ---------------- edge-attr scalar terms (all 3 convs in one pass) ----------------
__global__ void wa_k(const float* __restrict__ We2, const float* __restrict__ ae2,
                     const float* __restrict__ Wemu, const float* __restrict__ aemu,
                     const float* __restrict__ Wels, const float* __restrict__ aels,
                     float* __restrict__ wa) {
    int t = threadIdx.x;
    if (t < 16)      { float s = 0; for (int j = 0; j < 128; j++) s += We2[t * 128 + j] * ae2[j]; wa[t] = s; }
    else if (t < 32) { int r = t - 16; float s = 0; for (int j = 0; j < 64; j++) s += Wemu[r * 64 + j] * aemu[j]; wa[t] = s; }
    else if (t < 48) { int r = t - 32; float s = 0; for (int j = 0; j < 64; j++) s += Wels[r * 64 + j] * aels[j]; wa[t] = s; }
}

__global__ void zero4_k(float* a, float* b, float* c, float* d, int n) {
    for (int i = blockIdx.x * blockDim.x + threadIdx.x; i < n; i += gridDim.x * blockDim.x) {
        a[i] = 0.f; b[i] = 0.f; c[i] = 0.f; d[i] = 0.f;
    }
}

__global__ void eterms_k(const float* __restrict__ ea, const int* __restrict__ dst,
                         const float* __restrict__ wa,
                         float* __restrict__ T2, float* __restrict__ Tmu, float* __restrict__ Tls,
                         float* ts2, float* tsmu, float* tsls, float* cnt, int E) {
    __shared__ float ws[48];
    if (threadIdx.x < 48) ws[threadIdx.x] = wa[threadIdx.x];
    __syncthreads();
    for (int e = blockIdx.x * blockDim.x + threadIdx.x; e < E; e += gridDim.x * blockDim.x) {
        const float4* p = (const float4*)(ea + (size_t)e * 16);
        float t2 = 0.f, tm = 0.f, tl = 0.f;
#pragma unroll
        for (int q = 0; q < 4; q++) {
            float4 v = p[q];
            t2 += v.x * ws[q * 4 + 0] + v.y * ws[q * 4 + 1] + v.z * ws[q * 4 + 2] + v.w * ws[q * 4 + 3];
            tm += v.x * ws[16 + q * 4 + 0] + v.y * ws[16 + q * 4 + 1] + v.z * ws[16 + q * 4 + 2] + v.w * ws[16 + q * 4 + 3];
            tl += v.x * ws[32 + q * 4 + 0] + v.y * ws[32 + q * 4 + 1] + v.z * ws[32 + q * 4 + 2] + v.w * ws[32 + q * 4 + 3];
        }
        T2[e] = t2; Tmu[e] = tm; Tls[e] = tl;
        int d = dst[e];
        atomicAdd(&ts2[d], t2); atomicAdd(&tsmu[d], tm); atomicAdd(&tsls[d], tl);
        atomicAdd(&cnt[d], 1.f);
    }
}

__global__ void selfterm_k(const float* ts2, const float* tsmu, const float* tsls, const float* cnt,
                           float* st2, float* stmu, float* stls, int n) {
    for (int i = blockIdx.x * blockDim.x + threadIdx.x; i < n; i += gridDim.x * blockDim.x) {
        float c = fmaxf(cnt[i], 1.f);
        st2[i] = ts2[i] / c; stmu[i] = tsmu[i] / c; stls[i] = tsls[i] / c;
    }
}

// ---------------- node scalar (a_src·h, a_dst·h) + self-logit init ----------------
__global__ void scal128_k(const float* __restrict__ h, const float* __restrict__ asrc,
                          const float* __restrict__ adst, const float* __restrict__ st,
                          float* as_, float* ad_, float* m_, float* sl_, int n) {
    int lane = threadIdx.x & 31;
    int w = (blockIdx.x * blockDim.x + threadIdx.x) >> 5;
    int nw = (gridDim.x * blockDim.x) >> 5;
    float4 a4 = ((const float4*)asrc)[lane];
    float4 d4 = ((const float4*)adst)[lane];
    for (int i = w; i < n; i += nw) {
        float4 x = ((const float4*)(h + (size_t)i * 128))[lane];
        float s = x.x * a4.x + x.y * a4.y + x.z * a4.z + x.w * a4.w;
        float d = x.x * d4.x + x.y * d4.y + x.z * d4.z + x.w * d4.w;
#pragma unroll
        for (int o = 16; o; o >>= 1) { s += __shfl_xor_sync(FULL, s, o); d += __shfl_xor_sync(FULL, d, o); }
        if (lane == 0) {
            as_[i] = s; ad_[i] = d;
            float t = st ? st[i] : 0.f;
            float l = leaky(s + d + t);
            m_[i] = l; sl_[i] = l;
        }
    }
}

__global__ void scal64_k(const float* __restrict__ h, const float* __restrict__ asrc,
                         const float* __restrict__ adst, const float* __restrict__ st,
                         float* as_, float* ad_, float* m_, float* sl_, int n) {
    int lane = threadIdx.x & 31;
    int w = (blockIdx.x * blockDim.x + threadIdx.x) >> 5;
    int nw = (gridDim.x * blockDim.x) >> 5;
    float2 a2 = ((const float2*)asrc)[lane];
    float2 d2 = ((const float2*)adst)[lane];
    for (int i = w; i < n; i += nw) {
        float2 x = ((const float2*)(h + (size_t)i * 64))[lane];
        float s = x.x * a2.x + x.y * a2.y;
        float d = x.x * d2.x + x.y * d2.y;
#pragma unroll
        for (int o = 16; o; o >>= 1) { s += __shfl_xor_sync(FULL, s, o); d += __shfl_xor_sync(FULL, d, o); }
        if (lane == 0) {
            as_[i] = s; ad_[i] = d;
            float t = st ? st[i] : 0.f;
            float l = leaky(s + d + t);
            m_[i] = l; sl_[i] = l;
        }
    }
}

// ---------------- softmax passes ----------------
__global__ void edge_logit_k(const int* __restrict__ src, const int* __restrict__ dst,
                             const float* __restrict__ T, const float* __restrict__ as_,
                             const float* __restrict__ ad_, float* L, float* m_, int E) {
    for (int e = blockIdx.x * blockDim.x + threadIdx.x; e < E; e += gridDim.x * blockDim.x) {
        int s = src[e], d = dst[e];
        float t = T ? T[e] : 0.f;
        float l = leaky(as_[s] + ad_[d] + t);
        L[e] = l;
        atomicMaxF(&m_[d], l);
    }
}

__global__ void edge_logit2_k(const int* __restrict__ src, const int* __restrict__ dst,
                              const float* __restrict__ Ta, const float* __restrict__ Tb,
                              const float* as1, const float* ad1, const float* as2, const float* ad2,
                              float* L1, float* L2, float* m1, float* m2, int E) {
    for (int e = blockIdx.x * blockDim.x + threadIdx.x; e < E; e += gridDim.x * blockDim.x) {
        int s = src[e], d = dst[e];
        float la = leaky(as1[s] + ad1[d] + Ta[e]);
        float lb = leaky(as2[s] + ad2[d] + Tb[e]);
        L1[e] = la; L2[e] = lb;
        atomicMaxF(&m1[d], la);
        atomicMaxF(&m2[d], lb);
    }
}

__global__ void node_exp_k(const float* sl, const float* m_, float* sum_, float* sa, int n) {
    for (int i = blockIdx.x * blockDim.x + threadIdx.x; i < n; i += gridDim.x * blockDim.x) {
        float a = __expf(sl[i] - m_[i]);
        sum_[i] = a; sa[i] = a;
    }
}

__global__ void edge_exp_k(const int* __restrict__ dst, float* L, const float* m_, float* sum_, int E) {
    for (int e = blockIdx.x * blockDim.x + threadIdx.x; e < E; e += gridDim.x * blockDim.x) {
        int d = dst[e];
        float a = __expf(L[e] - m_[d]);
        L[e] = a;
        atomicAdd(&sum_[d], a);
    }
}

__global__ void edge_exp2_k(const int* __restrict__ dst, float* L1, float* L2,
                            const float* m1, const float* m2, float* s1, float* s2, int E) {
    for (int e = blockIdx.x * blockDim.x + threadIdx.x; e < E; e += gridDim.x * blockDim.x) {
        int d = dst[e];
        float a = __expf(L1[e] - m1[d]);
        float b = __expf(L2[e] - m2[d]);
        L1[e] = a; L2[e] = b;
        atomicAdd(&s1[d], a);
        atomicAdd(&s2[d], b);
    }
}

// ---------------- out init (bias + self-loop term) ----------------
__global__ void init128_k(const float* __restrict__ h, const float* __restrict__ bias,
                          const float* sa, const float* sm, float* __restrict__ out, int n) {
    int lane = threadIdx.x & 31;
    int w = (blockIdx.x * blockDim.x + threadIdx.x) >> 5;
    int nw = (gridDim.x * blockDim.x) >> 5;
    float4 b4 = ((const float4*)bias)[lane];
    for (int i = w; i < n; i += nw) {
        float wt = sa[i] / (sm[i] + 1e-16f);
        float4 x = ((const float4*)(h + (size_t)i * 128))[lane];
        float4 o;
        o.x = b4.x + wt * x.x; o.y = b4.y + wt * x.y;
        o.z = b4.z + wt * x.z; o.w = b4.w + wt * x.w;
        ((float4*)(out + (size_t)i * 128))[lane] = o;
    }
}

__global__ void init64_k(const float* __restrict__ h, const float* __restrict__ bias,
                         const float* sa, const float* sm, float* __restrict__ out, int n) {
    int lane = threadIdx.x & 31;
    int w = (blockIdx.x * blockDim.x + threadIdx.x) >> 5;
    int nw = (gridDim.x * blockDim.x) >> 5;
    float2 b2 = ((const float2*)bias)[lane];
    for (int i = w; i < n; i += nw) {
        float wt = sa[i] / (sm[i] + 1e-16f);
        float2 x = ((const float2*)(h + (size_t)i * 64))[lane];
        float2 o;
        o.x = b2.x + wt * x.x; o.y = b2.y + wt * x.y;
        ((float2*)(out + (size_t)i * 64))[lane] = o;
    }
}

// ---------------- scatter (warp per edge, vector red) ----------------
__global__ void scatter128_k(const int* __restrict__ src, const int* __restrict__ dst,
                             const float* __restrict__ L, const float* __restrict__ sum_,
                             const float* __restrict__ h, float* __restrict__ out, int E) {
    int lane = threadIdx.x & 31;
    int w = (blockIdx.x * blockDim.x + threadIdx.x) >> 5;
    int nw = (gridDim.x * blockDim.x) >> 5;
    for (int e = w; e < E; e += nw) {
        int s = 0, d = 0; float wt = 0.f;
        if (lane == 0) {
            s = src[e]; d = dst[e];
            wt = L[e] / (sum_[d] + 1e-16f);
        }
        s = __shfl_sync(FULL, s, 0);
        d = __shfl_sync(FULL, d, 0);
        wt = __shfl_sync(FULL, wt, 0);
        float4 v = ((const float4*)h)[(size_t)s * 32 + lane];
        v.x *= wt; v.y *= wt; v.z *= wt; v.w *= wt;
        redAdd4(out + (size_t)d * 128 + lane * 4, v);
    }
}

__global__ void scatter_muls_k(const int* __restrict__ src, const int* __restrict__ dst,
                               const float* __restrict__ Lmu, const float* __restrict__ Lls,
                               const float* __restrict__ smu, const float* __restrict__ sls,
                               const float* __restrict__ hmu, const float* __restrict__ hls,
                               float* __restrict__ omu, float* __restrict__ ols, int E) {
    int lane = threadIdx.x & 31;
    int w = (blockIdx.x * blockDim.x + threadIdx.x) >> 5;
    int nw = (gridDim.x * blockDim.x) >> 5;
    const float4* hp = (const float4*)((lane & 16) ? hls : hmu);
    float* op = (lane & 16) ? ols : omu;
    int lh = lane & 15;
    for (int e = w; e < E; e += nw) {
        int s = 0, d = 0;
        if (lane == 0) { s = src[e]; d = dst[e]; }
        s = __shfl_sync(FULL, s, 0);
        d = __shfl_sync(FULL, d, 0);
        float wt = 0.f;
        if ((lane & 15) == 0)
            wt = (lane < 16) ? Lmu[e] / (smu[d] + 1e-16f) : Lls[e] / (sls[d] + 1e-16f);
        wt = __shfl_sync(FULL, wt, lane & 16);
        float4 v = hp[(size_t)s * 16 + lh];
        v.x *= wt; v.y *= wt; v.z *= wt; v.w *= wt;
        redAdd4(op + (size_t)d * 64 + lh * 4, v);
    }
}

// ---------------- epilogues ----------------
__global__ void relu_k(float* p, int n4) {
    for (int i = blockIdx.x * blockDim.x + threadIdx.x; i < n4; i += gridDim.x * blockDim.x) {
        float4 v = ((float4*)p)[i];
        v.x = fmaxf(v.x, 0.f); v.y = fmaxf(v.y, 0.f);
        v.z = fmaxf(v.z, 0.f); v.w = fmaxf(v.w, 0.f);
        ((float4*)p)[i] = v;
    }
}

__global__ void relu_res_k(float* B, const float* __restrict__ D, const float* __restrict__ br, int n4) {
    for (int i = blockIdx.x * blockDim.x + threadIdx.x; i < n4; i += gridDim.x * blockDim.x) {
        float4 b = ((float4*)B)[i];
        float4 d = ((const float4*)D)[i];
        float4 r = ((const float4*)br)[i & 31];
        b.x = fmaxf(b.x, 0.f) + d.x + r.x;
        b.y = fmaxf(b.y, 0.f) + d.y + r.y;
        b.z = fmaxf(b.z, 0.f) + d.z + r.z;
        b.w = fmaxf(b.w, 0.f) + d.w + r.w;
        ((float4*)B)[i] = b;
    }
}

// ---------------- host ----------------
static float* gsa(const void* s) { void* p = nullptr; cudaGetSymbolAddress(&p, s); return (float*)p; }

extern "C" void kernel_launch(void* const* d_in, const int* in_sizes, int n_in,
                              void* d_out, int out_size) {
    const float* x    = (const float*)d_in[0];
    const int*   ei   = (const int*)d_in[1];
    const float* ea   = (const float*)d_in[2];
    const float* W1   = (const float*)d_in[3];
    const float* a1s  = (const float*)d_in[4];
    const float* a1d  = (const float*)d_in[5];
    const float* b1   = (const float*)d_in[6];
    const float* W2   = (const float*)d_in[7];
    const float* a2s  = (const float*)d_in[8];
    const float* a2d  = (const float*)d_in[9];
    const float* b2   = (const float*)d_in[10];
    const float* We2  = (const float*)d_in[11];
    const float* ae2  = (const float*)d_in[12];
    const float* Wr   = (const float*)d_in[13];
    const float* br   = (const float*)d_in[14];
    const float* Wmu  = (const float*)d_in[15];
    const float* amus = (const float*)d_in[16];
    const float* amud = (const float*)d_in[17];
    const float* bmu  = (const float*)d_in[18];
    const float* Wemu = (const float*)d_in[19];
    const float* aemu = (const float*)d_in[20];
    const float* Wls  = (const float*)d_in[21];
    const float* alss = (const float*)d_in[22];
    const float* alsd = (const float*)d_in[23];
    const float* bls  = (const float*)d_in[24];
    const float* Wels = (const float*)d_in[25];
    const float* aels = (const float*)d_in[26];

    const int n = in_sizes[0] / 128;
    const int E = in_sizes[1] / 2;
    const int* src = ei;
    const int* dst = ei + E;
    float* out_mu = (float*)d_out;
    float* out_ls = out_mu + (size_t)n * 64;

    float* A    = gsa(g_A);
    float* B    = gsa(g_B);
    float* D    = gsa(g_D);
    float* hmu  = gsa(g_hmu);
    float* hls  = gsa(g_hls);
    float* L1   = gsa(g_L1);
    float* L2   = gsa(g_L2);
    float* T2   = gsa(g_T2);
    float* Tmu  = gsa(g_Tmu);
    float* Tls  = gsa(g_Tls);
    float* as1  = gsa(g_as1);  float* ad1 = gsa(g_ad1);
    float* as2  = gsa(g_as2);  float* ad2 = gsa(g_ad2);
    float* m1   = gsa(g_m1);   float* m2  = gsa(g_m2);
    float* sum1 = gsa(g_sum1); float* sum2 = gsa(g_sum2);
    float* sa1  = gsa(g_sa1);  float* sa2 = gsa(g_sa2);
    float* sl1  = gsa(g_sl1);  float* sl2 = gsa(g_sl2);
    float* ts2  = gsa(g_ts2);  float* tsmu = gsa(g_tsmu); float* tsls = gsa(g_tsls);
    float* cnt  = gsa(g_cnt);
    float* st2  = gsa(g_st2);  float* stmu = gsa(g_stmu); float* stls = gsa(g_stls);
    float* wa   = gsa(g_wa);

    const int NB  = (n + 255) / 256;          // thread-per-node
    const int NW  = (n + 7) / 8;              // warp-per-node (256-thread blocks)
    const int EB  = (E + 255) / 256;          // thread-per-edge
    const int EW  = (E + 7) / 8;              // warp-per-edge (256-thread blocks)
    const int GV  = ((n * 32) + 255) / 256;   // float4-elementwise over [n,128]
    const int GM  = (n + 7) / 8;              // gemm: 8 rows/block

    // edge-attr scalar terms (shared by conv2 / mu / ls)
    zero4_k<<<NB, 256>>>(ts2, tsmu, tsls, cnt, n);
    wa_k<<<1, 64>>>(We2, ae2, Wemu, aemu, Wels, aels, wa);
    eterms_k<<<EB, 256>>>(ea, dst, wa, T2, Tmu, Tls, ts2, tsmu, tsls, cnt, E);
    selfterm_k<<<NB, 256>>>(ts2, tsmu, tsls, cnt, st2, stmu, stls, n);

    // residual projection (independent)
    gemm_k<128><<<GM, 128>>>(x, Wr, D, n);

    // ---- conv1 ----
    gemm_k<128><<<GM, 128>>>(x, W1, A, n);
    scal128_k<<<NW, 256>>>(A, a1s, a1d, nullptr, as1, ad1, m1, sl1, n);
    edge_logit_k<<<EB, 256>>>(src, dst, nullptr, as1, ad1, L1, m1, E);
    node_exp_k<<<NB, 256>>>(sl1, m1, sum1, sa1, n);
    edge_exp_k<<<EB, 256>>>(dst, L1, m1, sum1, E);
    init128_k<<<NW, 256>>>(A, b1, sa1, sum1, B, n);
    scatter128_k<<<EW, 256>>>(src, dst, L1, sum1, A, B, E);
    relu_k<<<GV, 256>>>(B, n * 32);

    // ---- conv2 ----
    gemm_k<128><<<GM, 128>>>(B, W2, A, n);
    scal128_k<<<NW, 256>>>(A, a2s, a2d, st2, as1, ad1, m1, sl1, n);
    edge_logit_k<<<EB, 256>>>(src, dst, T2, as1, ad1, L1, m1, E);
    node_exp_k<<<NB, 256>>>(sl1, m1, sum1, sa1, n);
    edge_exp_k<<<EB, 256>>>(dst, L1, m1, sum1, E);
    init128_k<<<NW, 256>>>(A, b2, sa1, sum1, B, n);
    scatter128_k<<<EW, 256>>>(src, dst, L1, sum1, A, B, E);
    relu_res_k<<<GV, 256>>>(B, D, br, n * 32);

    // ---- conv_mu + conv_logstd (fused edge passes) ----
    gemm_k<64><<<GM, 64>>>(B, Wmu, hmu, n);
    gemm_k<64><<<GM, 64>>>(B, Wls, hls, n);
    scal64_k<<<NW, 256>>>(hmu, amus, amud, stmu, as1, ad1, m1, sl1, n);
    scal64_k<<<NW, 256>>>(hls, alss, alsd, stls, as2, ad2, m2, sl2, n);
    edge_logit2_k<<<EB, 256>>>(src, dst, Tmu, Tls, as1, ad1, as2, ad2, L1, L2, m1, m2, E);
    node_exp_k<<<NB, 256>>>(sl1, m1, sum1, sa1, n);
    node_exp_k<<<NB, 256>>>(sl2, m2, sum2, sa2, n);
    edge_exp2_k<<<EB, 256>>>(dst, L1, L2, m1, m2, sum1, sum2, E);
    init64_k<<<NW, 256>>>(hmu, bmu, sa1, sum1, out_mu, n);
    init64_k<<<NW, 256>>>(hls, bls, sa2, sum2, out_ls, n);
    scatter_muls_k<<<EW, 256>>>(src, dst, L1, L2, sum1, sum2, hmu, hls, out_mu, out_ls, E);
}

// round 2
// speedup vs baseline: 2.0539x; 2.0539x over previous
#include <cuda_runtime.h>
#include <math.h>

#define NMAX 100000
#define EMAX 1600000
#define FULL 0xffffffffu

// ---------------- static scratch ----------------
__device__ float g_A[NMAX * 128];
__device__ float g_B[NMAX * 128];
__device__ float g_D[NMAX * 128];
__device__ float g_hmu[NMAX * 64];
__device__ float g_hls[NMAX * 64];
__device__ float g_T2e[EMAX], g_Tmue[EMAX], g_Tlse[EMAX];   // edge order
__device__ float g_cT2[EMAX], g_cTmu[EMAX], g_cTls[EMAX];   // csr order
__device__ int   g_csrc[EMAX];                              // csr src ids
__device__ int   g_cnt[NMAX];
__device__ int   g_off[NMAX + 1];
__device__ int   g_woff[NMAX];
__device__ float g_as1[NMAX], g_ad1[NMAX], g_as2[NMAX], g_ad2[NMAX];
__device__ float g_wa[48];

__device__ __forceinline__ float leaky(float v) { return v > 0.f ? v : 0.2f * v; }

// ---------------- We@ae precompute ----------------
__global__ void wa_k(const float* __restrict__ We2, const float* __restrict__ ae2,
                     const float* __restrict__ Wemu, const float* __restrict__ aemu,
                     const float* __restrict__ Wels, const float* __restrict__ aels,
                     float* __restrict__ wa) {
    int t = threadIdx.x;
    if (t < 16)      { float s = 0; for (int j = 0; j < 128; j++) s += We2[t * 128 + j] * ae2[j]; wa[t] = s; }
    else if (t < 32) { int r = t - 16; float s = 0; for (int j = 0; j < 64; j++) s += Wemu[r * 64 + j] * aemu[j]; wa[t] = s; }
    else if (t < 48) { int r = t - 32; float s = 0; for (int j = 0; j < 64; j++) s += Wels[r * 64 + j] * aels[j]; wa[t] = s; }
}

__global__ void zeroi_k(int* a, int n) {
    for (int i = blockIdx.x * blockDim.x + threadIdx.x; i < n; i += gridDim.x * blockDim.x) a[i] = 0;
}

// edge-attr scalar terms + dst histogram
__global__ void eterms_k(const float* __restrict__ ea, const int* __restrict__ dst,
                         const float* __restrict__ wa,
                         float* __restrict__ T2, float* __restrict__ Tmu, float* __restrict__ Tls,
                         int* __restrict__ cnt, int E) {
    __shared__ float ws[48];
    if (threadIdx.x < 48) ws[threadIdx.x] = wa[threadIdx.x];
    __syncthreads();
    for (int e = blockIdx.x * blockDim.x + threadIdx.x; e < E; e += gridDim.x * blockDim.x) {
        const float4* p = (const float4*)(ea + (size_t)e * 16);
        float t2 = 0.f, tm = 0.f, tl = 0.f;
#pragma unroll
        for (int q = 0; q < 4; q++) {
            float4 v = p[q];
            t2 += v.x * ws[q*4+0] + v.y * ws[q*4+1] + v.z * ws[q*4+2] + v.w * ws[q*4+3];
            tm += v.x * ws[16+q*4+0] + v.y * ws[16+q*4+1] + v.z * ws[16+q*4+2] + v.w * ws[16+q*4+3];
            tl += v.x * ws[32+q*4+0] + v.y * ws[32+q*4+1] + v.z * ws[32+q*4+2] + v.w * ws[32+q*4+3];
        }
        T2[e] = t2; Tmu[e] = tm; Tls[e] = tl;
        atomicAdd(&cnt[dst[e]], 1);
    }
}

// single-block exclusive scan over cnt -> off, woff
__global__ void scan_k(const int* __restrict__ cnt, int* __restrict__ off,
                       int* __restrict__ woff, int n) {
    __shared__ int ssum[1024];
    int t = threadIdx.x;
    int ipt = (n + 1023) / 1024;
    int b = t * ipt, e = min(b + ipt, n);
    int s = 0;
    for (int i = b; i < e; i++) s += cnt[i];
    ssum[t] = s;
    __syncthreads();
    for (int o = 1; o < 1024; o <<= 1) {
        int v = (t >= o) ? ssum[t - o] : 0;
        __syncthreads();
        ssum[t] += v;
        __syncthreads();
    }
    int base = (t == 0) ? 0 : ssum[t - 1];
    for (int i = b; i < e; i++) { off[i] = base; woff[i] = base; base += cnt[i]; }
    if (t == 1023) off[n] = ssum[1023];
}

// place edges into CSR slots
__global__ void place_k(const int* __restrict__ src, const int* __restrict__ dst,
                        const float* __restrict__ T2, const float* __restrict__ Tmu,
                        const float* __restrict__ Tls,
                        int* __restrict__ woff, int* __restrict__ csrc,
                        float* __restrict__ cT2, float* __restrict__ cTmu,
                        float* __restrict__ cTls, int E) {
    for (int e = blockIdx.x * blockDim.x + threadIdx.x; e < E; e += gridDim.x * blockDim.x) {
        int d = dst[e];
        int p = atomicAdd(&woff[d], 1);
        csrc[p] = src[e];
        cT2[p] = T2[e]; cTmu[p] = Tmu[e]; cTls[p] = Tls[e];
    }
}

// ---------------- GEMM: Y = X[n,128] @ W[128,128], optionally split cols a|b ----------------
// block 256 threads: tx=col-group (4 cols), ty=row-group (8 rows), tile = 64 rows x 128 cols
__global__ void gemm_k(const float* __restrict__ X,
                       const float* __restrict__ Wa, const float* __restrict__ Wb,
                       float* __restrict__ Ya, float* __restrict__ Yb,
                       int Ca, int n) {
    extern __shared__ float sh[];            // Wsh[128*128] + Xs[64*128]
    float* Wsh = sh;
    float* Xs  = sh + 128 * 128;
    const int tid = threadIdx.x;
    const int tx = tid & 31, ty = tid >> 5;
    const int Cb = 128 - Ca;

    // load W (both halves) into Wsh[k][j]
    for (int idx = tid; idx < 128 * 32; idx += 256) {     // float4 granularity
        int k = idx >> 5, q = idx & 31;
        int j0 = q * 4;
        float4 v;
        if (j0 < Ca) v = *(const float4*)&Wa[(size_t)k * Ca + j0];
        else         v = *(const float4*)&Wb[(size_t)k * Cb + (j0 - Ca)];
        *(float4*)&Wsh[k * 128 + j0] = v;
    }

    int rt = blockIdx.x * 64;
    // load X tile (64 x 128)
    __syncthreads();
    for (int idx = tid; idx < 64 * 32; idx += 256) {
        int r = idx >> 5, q = idx & 31;
        float4 v = {0.f, 0.f, 0.f, 0.f};
        if (rt + r < n) v = *(const float4*)&X[(size_t)(rt + r) * 128 + q * 4];
        *(float4*)&Xs[r * 128 + q * 4] = v;
    }
    __syncthreads();

    float4 acc[8];
#pragma unroll
    for (int r = 0; r < 8; r++) acc[r] = make_float4(0.f, 0.f, 0.f, 0.f);

#pragma unroll 8
    for (int k = 0; k < 128; k++) {
        float4 w = *(float4*)&Wsh[k * 128 + tx * 4];
#pragma unroll
        for (int r = 0; r < 8; r++) {
            float xv = Xs[(ty * 8 + r) * 128 + k];
            acc[r].x = fmaf(xv, w.x, acc[r].x);
            acc[r].y = fmaf(xv, w.y, acc[r].y);
            acc[r].z = fmaf(xv, w.z, acc[r].z);
            acc[r].w = fmaf(xv, w.w, acc[r].w);
        }
    }

    int j0 = tx * 4;
#pragma unroll
    for (int r = 0; r < 8; r++) {
        int row = rt + ty * 8 + r;
        if (row < n) {
            if (j0 < Ca) *(float4*)&Ya[(size_t)row * Ca + j0] = acc[r];
            else         *(float4*)&Yb[(size_t)row * Cb + (j0 - Ca)] = acc[r];
        }
    }
}

// ---------------- node scalars as=a_src.h, ad=a_dst.h ----------------
__global__ void scal128_k(const float* __restrict__ h, const float* __restrict__ asrc,
                          const float* __restrict__ adst, float* __restrict__ as_,
                          float* __restrict__ ad_, int n) {
    int lane = threadIdx.x & 31;
    int w = (blockIdx.x * blockDim.x + threadIdx.x) >> 5;
    int nw = (gridDim.x * blockDim.x) >> 5;
    float4 a4 = ((const float4*)asrc)[lane];
    float4 d4 = ((const float4*)adst)[lane];
    for (int i = w; i < n; i += nw) {
        float4 x = ((const float4*)(h + (size_t)i * 128))[lane];
        float s = x.x * a4.x + x.y * a4.y + x.z * a4.z + x.w * a4.w;
        float d = x.x * d4.x + x.y * d4.y + x.z * d4.z + x.w * d4.w;
#pragma unroll
        for (int o = 16; o; o >>= 1) { s += __shfl_xor_sync(FULL, s, o); d += __shfl_xor_sync(FULL, d, o); }
        if (lane == 0) { as_[i] = s; ad_[i] = d; }
    }
}

__global__ void scal64_k(const float* __restrict__ h, const float* __restrict__ asrc,
                         const float* __restrict__ adst, float* __restrict__ as_,
                         float* __restrict__ ad_, int n) {
    int lane = threadIdx.x & 31;
    int w = (blockIdx.x * blockDim.x + threadIdx.x) >> 5;
    int nw = (gridDim.x * blockDim.x) >> 5;
    float2 a2 = ((const float2*)asrc)[lane];
    float2 d2 = ((const float2*)adst)[lane];
    for (int i = w; i < n; i += nw) {
        float2 x = ((const float2*)(h + (size_t)i * 64))[lane];
        float s = x.x * a2.x + x.y * a2.y;
        float d = x.x * d2.x + x.y * d2.y;
#pragma unroll
        for (int o = 16; o; o >>= 1) { s += __shfl_xor_sync(FULL, s, o); d += __shfl_xor_sync(FULL, d, o); }
        if (lane == 0) { as_[i] = s; ad_[i] = d; }
    }
}

// ---------------- fused GAT conv, C=128, warp per dst node ----------------
// out[i] = act( sum_e softmax(logit) * h[src] + bias )  (+residual)
__global__ void gat128_k(const int* __restrict__ off, const int* __restrict__ csrc,
                         const float* __restrict__ cT,
                         const float* __restrict__ as_, const float* __restrict__ ad_,
                         const float* __restrict__ h, const float* __restrict__ bias,
                         const float* __restrict__ Dres, const float* __restrict__ br,
                         float* __restrict__ out, int n) {
    int lane = threadIdx.x & 31;
    int w = (blockIdx.x * blockDim.x + threadIdx.x) >> 5;
    int nw = (gridDim.x * blockDim.x) >> 5;
    float4 b4 = ((const float4*)bias)[lane];
    for (int i = w; i < n; i += nw) {
        int s0 = off[i], s1 = off[i + 1];
        float asi = as_[i], adi = ad_[i];
        // pass 1: max logit (+ sum of T for self-loop mean)
        float mx = -1e30f, sT = 0.f;
        for (int j = s0 + lane; j < s1; j += 32) {
            float t = cT ? cT[j] : 0.f;
            float l = leaky(as_[csrc[j]] + adi + t);
            mx = fmaxf(mx, l);
            sT += t;
        }
#pragma unroll
        for (int o = 16; o; o >>= 1) {
            mx = fmaxf(mx, __shfl_xor_sync(FULL, mx, o));
            sT += __shfl_xor_sync(FULL, sT, o);
        }
        int deg = s1 - s0;
        float st = cT ? sT / fmaxf((float)deg, 1.f) : 0.f;
        float lself = leaky(asi + adi + st);
        mx = fmaxf(mx, lself);
        // pass 2: accumulate
        float4 acc = make_float4(0.f, 0.f, 0.f, 0.f);
        float sum = 0.f;
        for (int j = s0; j < s1; j++) {
            int s = csrc[j];
            float t = cT ? cT[j] : 0.f;
            float wg = __expf(leaky(as_[s] + adi + t) - mx);
            sum += wg;
            float4 v = ((const float4*)h)[(size_t)s * 32 + lane];
            acc.x = fmaf(wg, v.x, acc.x); acc.y = fmaf(wg, v.y, acc.y);
            acc.z = fmaf(wg, v.z, acc.z); acc.w = fmaf(wg, v.w, acc.w);
        }
        float wself = __expf(lself - mx);
        sum += wself;
        {
            float4 v = ((const float4*)h)[(size_t)i * 32 + lane];
            acc.x = fmaf(wself, v.x, acc.x); acc.y = fmaf(wself, v.y, acc.y);
            acc.z = fmaf(wself, v.z, acc.z); acc.w = fmaf(wself, v.w, acc.w);
        }
        float inv = 1.f / (sum + 1e-16f);
        float4 o;
        o.x = fmaxf(acc.x * inv + b4.x, 0.f);
        o.y = fmaxf(acc.y * inv + b4.y, 0.f);
        o.z = fmaxf(acc.z * inv + b4.z, 0.f);
        o.w = fmaxf(acc.w * inv + b4.w, 0.f);
        if (Dres) {
            float4 d = ((const float4*)Dres)[(size_t)i * 32 + lane];
            float4 r = ((const float4*)br)[lane];
            o.x += d.x + r.x; o.y += d.y + r.y; o.z += d.z + r.z; o.w += d.w + r.w;
        }
        ((float4*)out)[(size_t)i * 32 + lane] = o;
    }
}

// ---------------- fused mu+ls conv, C=64 each, warp per dst node ----------------
__global__ void gat64x2_k(const int* __restrict__ off, const int* __restrict__ csrc,
                          const float* __restrict__ cTa, const float* __restrict__ cTb,
                          const float* __restrict__ asa, const float* __restrict__ ada,
                          const float* __restrict__ asb, const float* __restrict__ adb,
                          const float* __restrict__ ha, const float* __restrict__ hb,
                          const float* __restrict__ ba, const float* __restrict__ bb,
                          float* __restrict__ oa, float* __restrict__ ob, int n) {
    int lane = threadIdx.x & 31;
    int half = lane >> 4, lh = lane & 15;
    int w = (blockIdx.x * blockDim.x + threadIdx.x) >> 5;
    int nw = (gridDim.x * blockDim.x) >> 5;
    const float4* hp = (const float4*)(half ? hb : ha);
    const float4* bp = (const float4*)(half ? bb : ba);
    float* op = half ? ob : oa;
    float4 b4 = bp[lh];
    for (int i = w; i < n; i += nw) {
        int s0 = off[i], s1 = off[i + 1];
        float asia = asa[i], adia = ada[i];
        float asib = asb[i], adib = adb[i];
        float mxa = -1e30f, mxb = -1e30f, sTa = 0.f, sTb = 0.f;
        for (int j = s0 + lane; j < s1; j += 32) {
            int s = csrc[j];
            float ta = cTa[j], tb = cTb[j];
            mxa = fmaxf(mxa, leaky(asa[s] + adia + ta));
            mxb = fmaxf(mxb, leaky(asb[s] + adib + tb));
            sTa += ta; sTb += tb;
        }
#pragma unroll
        for (int o = 16; o; o >>= 1) {
            mxa = fmaxf(mxa, __shfl_xor_sync(FULL, mxa, o));
            mxb = fmaxf(mxb, __shfl_xor_sync(FULL, mxb, o));
            sTa += __shfl_xor_sync(FULL, sTa, o);
            sTb += __shfl_xor_sync(FULL, sTb, o);
        }
        float degc = fmaxf((float)(s1 - s0), 1.f);
        float lsa = leaky(asia + adia + sTa / degc);
        float lsb = leaky(asib + adib + sTb / degc);
        mxa = fmaxf(mxa, lsa); mxb = fmaxf(mxb, lsb);

        float4 acc = make_float4(0.f, 0.f, 0.f, 0.f);
        float suma = 0.f, sumb = 0.f;
        for (int j = s0; j < s1; j++) {
            int s = csrc[j];
            float wga = __expf(leaky(asa[s] + adia + cTa[j]) - mxa);
            float wgb = __expf(leaky(asb[s] + adib + cTb[j]) - mxb);
            suma += wga; sumb += wgb;
            float wg = half ? wgb : wga;
            float4 v = hp[(size_t)s * 16 + lh];
            acc.x = fmaf(wg, v.x, acc.x); acc.y = fmaf(wg, v.y, acc.y);
            acc.z = fmaf(wg, v.z, acc.z); acc.w = fmaf(wg, v.w, acc.w);
        }
        float wsa = __expf(lsa - mxa), wsb = __expf(lsb - mxb);
        suma += wsa; sumb += wsb;
        {
            float wg = half ? wsb : wsa;
            float4 v = hp[(size_t)i * 16 + lh];
            acc.x = fmaf(wg, v.x, acc.x); acc.y = fmaf(wg, v.y, acc.y);
            acc.z = fmaf(wg, v.z, acc.z); acc.w = fmaf(wg, v.w, acc.w);
        }
        float inv = 1.f / ((half ? sumb : suma) + 1e-16f);
        float4 o;
        o.x = acc.x * inv + b4.x; o.y = acc.y * inv + b4.y;
        o.z = acc.z * inv + b4.z; o.w = acc.w * inv + b4.w;
        ((float4*)op)[(size_t)i * 16 + lh] = o;
    }
}

// ---------------- host ----------------
static void* gsa(const void* s) { void* p = nullptr; cudaGetSymbolAddress(&p, s); return p; }

extern "C" void kernel_launch(void* const* d_in, const int* in_sizes, int n_in,
                              void* d_out, int out_size) {
    const float* x    = (const float*)d_in[0];
    const int*   ei   = (const int*)d_in[1];
    const float* ea   = (const float*)d_in[2];
    const float* W1   = (const float*)d_in[3];
    const float* a1s  = (const float*)d_in[4];
    const float* a1d  = (const float*)d_in[5];
    const float* b1   = (const float*)d_in[6];
    const float* W2   = (const float*)d_in[7];
    const float* a2s  = (const float*)d_in[8];
    const float* a2d  = (const float*)d_in[9];
    const float* b2   = (const float*)d_in[10];
    const float* We2  = (const float*)d_in[11];
    const float* ae2  = (const float*)d_in[12];
    const float* Wr   = (const float*)d_in[13];
    const float* br   = (const float*)d_in[14];
    const float* Wmu  = (const float*)d_in[15];
    const float* amus = (const float*)d_in[16];
    const float* amud = (const float*)d_in[17];
    const float* bmu  = (const float*)d_in[18];
    const float* Wemu = (const float*)d_in[19];
    const float* aemu = (const float*)d_in[20];
    const float* Wls  = (const float*)d_in[21];
    const float* alss = (const float*)d_in[22];
    const float* alsd = (const float*)d_in[23];
    const float* bls  = (const float*)d_in[24];
    const float* Wels = (const float*)d_in[25];
    const float* aels = (const float*)d_in[26];

    const int n = in_sizes[0] / 128;
    const int E = in_sizes[1] / 2;
    const int* src = ei;
    const int* dst = ei + E;
    float* out_mu = (float*)d_out;
    float* out_ls = out_mu + (size_t)n * 64;

    float* A    = (float*)gsa(g_A);
    float* B    = (float*)gsa(g_B);
    float* D    = (float*)gsa(g_D);
    float* hmu  = (float*)gsa(g_hmu);
    float* hls  = (float*)gsa(g_hls);
    float* T2e  = (float*)gsa(g_T2e);
    float* Tmue = (float*)gsa(g_Tmue);
    float* Tlse = (float*)gsa(g_Tlse);
    float* cT2  = (float*)gsa(g_cT2);
    float* cTmu = (float*)gsa(g_cTmu);
    float* cTls = (float*)gsa(g_cTls);
    int*   csrc = (int*)gsa(g_csrc);
    int*   cnt  = (int*)gsa(g_cnt);
    int*   off  = (int*)gsa(g_off);
    int*   woff = (int*)gsa(g_woff);
    float* as1  = (float*)gsa(g_as1);
    float* ad1  = (float*)gsa(g_ad1);
    float* as2  = (float*)gsa(g_as2);
    float* ad2  = (float*)gsa(g_ad2);
    float* wa   = (float*)gsa(g_wa);

    const int NB = (n + 255) / 256;
    const int EB = (E + 255) / 256;
    const int NW = (n + 7) / 8;                 // warp-per-node, 256-thr blocks
    const int GT = (n + 63) / 64;               // gemm row tiles
    const int GSMEM = (128 * 128 + 64 * 128) * 4;

    cudaFuncSetAttribute(gemm_k, cudaFuncAttributeMaxDynamicSharedMemorySize, GSMEM);

    // CSR build + edge-attr scalar terms
    zeroi_k<<<NB, 256>>>(cnt, n);
    wa_k<<<1, 64>>>(We2, ae2, Wemu, aemu, Wels, aels, wa);
    eterms_k<<<EB, 256>>>(ea, dst, wa, T2e, Tmue, Tlse, cnt, E);
    scan_k<<<1, 1024>>>(cnt, off, woff, n);
    place_k<<<EB, 256>>>(src, dst, T2e, Tmue, Tlse, woff, csrc, cT2, cTmu, cTls, E);

    // projections
    gemm_k<<<GT, 256, GSMEM>>>(x, W1, W1, A, A, 128, n);
    gemm_k<<<GT, 256, GSMEM>>>(x, Wr, Wr, D, D, 128, n);

    // conv1
    scal128_k<<<NW, 256>>>(A, a1s, a1d, as1, ad1, n);
    gat128_k<<<NW, 256>>>(off, csrc, nullptr, as1, ad1, A, b1, nullptr, nullptr, B, n);

    // conv2
    gemm_k<<<GT, 256, GSMEM>>>(B, W2, W2, A, A, 128, n);
    scal128_k<<<NW, 256>>>(A, a2s, a2d, as1, ad1, n);
    gat128_k<<<NW, 256>>>(off, csrc, cT2, as1, ad1, A, b2, D, br, B, n);

    // mu / logstd projections (fused, shared input read)
    gemm_k<<<GT, 256, GSMEM>>>(B, Wmu, Wls, hmu, hls, 64, n);
    scal64_k<<<NW, 256>>>(hmu, amus, amud, as1, ad1, n);
    scal64_k<<<NW, 256>>>(hls, alss, alsd, as2, ad2, n);
    gat64x2_k<<<NW, 256>>>(off, csrc, cTmu, cTls, as1, ad1, as2, ad2,
                           hmu, hls, bmu, bls, out_mu, out_ls, n);
}